// round 14
// baseline (speedup 1.0000x reference)
#include <cuda_runtime.h>
#include <cuda_fp16.h>
#include <cstdint>

#define B_SZ    16384
#define NSTATES 4096
#define GTOT    768
#define NACT    4

// ---------------- mma / ldmatrix / cp.async helpers -------------------------
__device__ __forceinline__ uint32_t smem_to_u32(const void* p) {
    uint32_t a;
    asm("{ .reg .u64 t; cvta.to.shared.u64 t, %1; cvt.u32.u64 %0, t; }" : "=r"(a) : "l"(p));
    return a;
}
#define CP_ASYNC16(dst, src) \
    asm volatile("cp.async.cg.shared.global [%0], [%1], 16;" :: "r"(dst), "l"(src))
#define CP_COMMIT() asm volatile("cp.async.commit_group;" ::: "memory")
#define CP_WAIT(n)  asm volatile("cp.async.wait_group %0;" :: "n"(n) : "memory")

#define LDSM_X4(r0, r1, r2, r3, a) \
    asm volatile("ldmatrix.sync.aligned.m8n8.x4.shared.b16 {%0,%1,%2,%3}, [%4];" \
        : "=r"(r0), "=r"(r1), "=r"(r2), "=r"(r3) : "r"(a))

#define MMA16816(d, a, b0v, b1v) \
    asm volatile("mma.sync.aligned.m16n8k16.row.col.f32.f16.f16.f32 " \
        "{%0,%1,%2,%3}, {%4,%5,%6,%7}, {%8,%9}, {%0,%1,%2,%3};" \
        : "+f"((d)[0]), "+f"((d)[1]), "+f"((d)[2]), "+f"((d)[3]) \
        : "r"((a)[0]), "r"((a)[1]), "r"((a)[2]), "r"((a)[3]), "r"(b0v), "r"(b1v))

// ---------------- device scratch --------------------------------------------
__device__ int d_off[NACT + 1];
__device__ int d_perm[B_SZ];
__device__ float d_gscratch[(size_t)B_SZ * GTOT];
__device__ __half d_Ah[(size_t)B_SZ * GTOT];      // g_next in fp16
__device__ __half d_Wh[(size_t)NSTATES * GTOT];   // W in fp16
__device__ __half d_Eh[(size_t)NSTATES * GTOT];   // emb in fp16
__device__ __half d_D0h[4 * 256 * 256];
__device__ __half d_D1h[4 * 256 * 256];
__device__ __half d_D2h[4 * 128 * 128];
__device__ __half d_D3h[4 * 128 * 128];

// ---------------- fused single-block counting sort --------------------------
__global__ void k_sort(const int* __restrict__ act) {
    __shared__ int cnt[NACT];
    __shared__ int cur[NACT];
    const int t = threadIdx.x;
    const int lane = t & 31;
    if (t < NACT) cnt[t] = 0;
    __syncthreads();
    for (int i = t; i < B_SZ; i += blockDim.x) {
        int a = act[i];
        unsigned mask = __match_any_sync(0xffffffffu, a);
        if (lane == (__ffs(mask) - 1)) atomicAdd(&cnt[a], __popc(mask));
    }
    __syncthreads();
    if (t == 0) {
        int s = 0;
        for (int a = 0; a < NACT; a++) { d_off[a] = s; cur[a] = s; s += cnt[a]; }
        d_off[NACT] = s;
    }
    __syncthreads();
    for (int i = t; i < B_SZ; i += blockDim.x) {
        int a = act[i];
        unsigned mask = __match_any_sync(0xffffffffu, a);
        int leader = __ffs(mask) - 1;
        int rank = __popc(mask & ((1u << lane) - 1u));
        int base = 0;
        if (lane == leader) base = atomicAdd(&cur[a], __popc(mask));
        base = __shfl_sync(0xffffffffu, base, leader);
        d_perm[base + rank] = i;
    }
}

// ---------------- fused fp32 -> fp16 conversion ------------------------------
#define CVT_NW   (NSTATES * GTOT / 4)        // 786432
#define CVT_ND01 (4 * 256 * 256 / 4)         // 65536
#define CVT_ND23 (4 * 128 * 128 / 4)         // 16384
#define CVT_TOT  (2 * CVT_NW + 2 * CVT_ND01 + 2 * CVT_ND23)

__global__ void k_convert(const float* __restrict__ W, const float* __restrict__ E,
                          const float* __restrict__ D0, const float* __restrict__ D1,
                          const float* __restrict__ D2, const float* __restrict__ D3) {
    int i = blockIdx.x * blockDim.x + threadIdx.x;
    const float* src; __half* dst;
    if (i < CVT_NW)                       { src = W;  dst = d_Wh; }
    else if ((i -= CVT_NW) < CVT_NW)      { src = E;  dst = d_Eh; }
    else if ((i -= CVT_NW) < CVT_ND01)    { src = D0; dst = d_D0h; }
    else if ((i -= CVT_ND01) < CVT_ND01)  { src = D1; dst = d_D1h; }
    else if ((i -= CVT_ND01) < CVT_ND23)  { src = D2; dst = d_D2h; }
    else if ((i -= CVT_ND23) < CVT_ND23)  { src = D3; dst = d_D3h; }
    else return;
    float4 w4 = ((const float4*)src)[i];
    ((__half2*)dst)[2 * i]     = __floats2half2_rn(w4.x, w4.y);
    ((__half2*)dst)[2 * i + 1] = __floats2half2_rn(w4.z, w4.w);
}

// ---------------- HMMA transition -------------------------------------------
// C[r,j] = sum_i Eh[state_r, moff+i] * Dh_a[jbase+j, i]; g_next = clip(g + C)
// Tile: 128 gathered rows x 64 cols, BK=64, 128 thr / 4 warps, warp 32x64.
#define TSM_PERM   0
#define TSM_STATE  512
#define TSM_TILES  1024
#define TSTG_B     24576                 // A 16K + B 8K
#define TOFF_B     16384
#define TSM_TOTAL  (TSM_TILES + 2 * TSTG_B)   // 50176

__global__ void __launch_bounds__(128, 4)
k_transition(const int* __restrict__ csi,
             const float* __restrict__ emb,
             float* __restrict__ gout)
{
    extern __shared__ char smem[];
    const uint32_t smem_base = smem_to_u32(smem);
    int* permS   = (int*)(smem + TSM_PERM);
    int* stateS  = (int*)(smem + TSM_STATE);

    const int jt = blockIdx.y;
    const int a  = blockIdx.z;
    int jbase, moff, nf; const __half* Dh;
    if (jt < 4)       { jbase = jt * 64;        moff = 0;   nf = 256; Dh = d_D0h; }
    else if (jt < 8)  { jbase = (jt - 4) * 64;  moff = 256; nf = 256; Dh = d_D1h; }
    else if (jt < 10) { jbase = (jt - 8) * 64;  moff = 512; nf = 128; Dh = d_D2h; }
    else              { jbase = (jt - 10) * 64; moff = 640; nf = 128; Dh = d_D3h; }

    const int row0   = d_off[a] + blockIdx.x * 128;
    const int rowEnd = d_off[a + 1];
    if (row0 >= rowEnd) return;
    const __half* __restrict__ Da = Dh + (size_t)a * nf * nf;

    const int t = threadIdx.x;
    const int lane = t & 31;
    const int wid  = t >> 5;              // 0..3, each warp: 32 rows x 64 cols
    {
        int r = row0 + t;
        if (r < rowEnd) { int b = d_perm[r]; permS[t] = b; stateS[t] = csi[b]; }
        else            { permS[t] = -1;     stateS[t] = 0; }
    }
    __syncthreads();

    const int NK = nf / 64;

    // stage loader: A = gathered fp16 emb rows (1 row per thread), B = D rows
    auto load_stage = [&](int kk, int stg) {
        const int kc = kk * 64;
        const uint32_t sbase = smem_base + TSM_TILES + stg * TSTG_B;
        const __half* arow = d_Eh + (size_t)stateS[t] * GTOT + moff + kc;
        #pragma unroll
        for (int ck = 0; ck < 8; ck++) {
            uint32_t sw = t * 128 + ((ck ^ (t & 7)) << 4);
            CP_ASYNC16(sbase + sw, arow + ck * 8);
        }
        const int rn = t >> 1;            // 0..63
        const int cb = (t & 1) * 4;
        const __half* brow = Da + (size_t)(jbase + rn) * nf + kc;
        #pragma unroll
        for (int q = 0; q < 4; q++) {
            int ck = cb + q;
            uint32_t sw = rn * 128 + ((ck ^ (rn & 7)) << 4);
            CP_ASYNC16(sbase + TOFF_B + sw, brow + ck * 8);
        }
    };

    float acc[2][8][4];
    #pragma unroll
    for (int mt = 0; mt < 2; mt++)
        #pragma unroll
        for (int nt = 0; nt < 8; nt++)
            #pragma unroll
            for (int q = 0; q < 4; q++) acc[mt][nt][q] = 0.f;

    const int lr  = lane & 15;
    const int lk8 = lane >> 4;

    load_stage(0, 0);
    CP_COMMIT();

    for (int kk = 0; kk < NK; kk++) {
        if (kk + 1 < NK) { load_stage(kk + 1, (kk + 1) & 1); CP_COMMIT(); CP_WAIT(1); }
        else             { CP_WAIT(0); }
        __syncthreads();

        const uint32_t sbase = smem_base + TSM_TILES + (kk & 1) * TSTG_B;
        #pragma unroll
        for (int ks = 0; ks < 4; ks++) {
            const int k8 = ks * 2 + lk8;
            uint32_t afr[2][4], bfr[4][4];
            #pragma unroll
            for (int mt = 0; mt < 2; mt++) {
                int row = wid * 32 + mt * 16 + lr;
                uint32_t ad = sbase + row * 128 + ((k8 ^ (row & 7)) << 4);
                LDSM_X4(afr[mt][0], afr[mt][1], afr[mt][2], afr[mt][3], ad);
            }
            #pragma unroll
            for (int np = 0; np < 4; np++) {
                int rn = np * 16 + lr;
                uint32_t bd = sbase + TOFF_B + rn * 128 + ((k8 ^ (rn & 7)) << 4);
                LDSM_X4(bfr[np][0], bfr[np][1], bfr[np][2], bfr[np][3], bd);
            }
            #pragma unroll
            for (int mt = 0; mt < 2; mt++)
                #pragma unroll
                for (int np = 0; np < 4; np++) {
                    MMA16816(acc[mt][2 * np],     afr[mt], bfr[np][0], bfr[np][2]);
                    MMA16816(acc[mt][2 * np + 1], afr[mt], bfr[np][1], bfr[np][3]);
                }
        }
        __syncthreads();
    }

    // epilogue: residual (fp32 emb) + clip; write gout fp32 + d_Ah fp16
    #pragma unroll
    for (int mt = 0; mt < 2; mt++) {
        int rl = wid * 32 + mt * 16 + (lane >> 2);
        #pragma unroll
        for (int half = 0; half < 2; half++) {
            int rr = rl + half * 8;
            int borig = permS[rr];
            if (borig < 0) continue;
            int state = stateS[rr];
            #pragma unroll
            for (int nt = 0; nt < 8; nt++) {
                int gcol = moff + jbase + nt * 8 + 2 * (lane & 3);
                float2 g2 = *(const float2*)(emb + (size_t)state * GTOT + gcol);
                float ox = fminf(fmaxf(g2.x + acc[mt][nt][2 * half],     -1.f), 1.f);
                float oy = fminf(fmaxf(g2.y + acc[mt][nt][2 * half + 1], -1.f), 1.f);
                *(float2*)(gout + (size_t)borig * GTOT + gcol) = make_float2(ox, oy);
                *(__half2*)(d_Ah + (size_t)borig * GTOT + gcol) = __floats2half2_rn(ox, oy);
            }
        }
    }
}

// ---------------- HMMA logits GEMM (R8 config: at legacy-pipe floor) ---------
#define GEMM_ITERS 12
#define STG_B      32768
#define OFF_B      16384
#define GSM_TOTAL  (3 * STG_B)               // 96 KB

__device__ __forceinline__ void g_load_stage(int it, int stg, int m0, int n0,
                                             int tid, uint32_t smem_base) {
    const int kc = it * 64;
    const int row = tid >> 1;
    const int cb  = (tid & 1) * 4;
    const uint32_t sbase = smem_base + stg * STG_B;
    const __half* ah = d_Ah + (size_t)(m0 + row) * GTOT + kc;
    const __half* bw = d_Wh + (size_t)(n0 + row) * GTOT + kc;
    #pragma unroll
    for (int c = 0; c < 4; c++) {
        int ck = cb + c;
        uint32_t sw = row * 128 + ((ck ^ (row & 7)) << 4);
        CP_ASYNC16(sbase + sw,          ah + ck * 8);
        CP_ASYNC16(sbase + OFF_B + sw,  bw + ck * 8);
    }
}

__global__ void __launch_bounds__(256, 2)
k_logits(const float* __restrict__ bias, float* __restrict__ out)
{
    extern __shared__ char smem[];
    const uint32_t smem_base = smem_to_u32(smem);
    const int tid  = threadIdx.x;
    const int lane = tid & 31;
    const int wid  = tid >> 5;
    const int wm   = wid >> 1;
    const int wn   = wid & 1;
    const int m0 = blockIdx.y * 128;
    const int n0 = blockIdx.x * 128;

    float acc[2][8][4];
    #pragma unroll
    for (int mt = 0; mt < 2; mt++)
        #pragma unroll
        for (int nt = 0; nt < 8; nt++)
            #pragma unroll
            for (int q = 0; q < 4; q++) acc[mt][nt][q] = 0.f;

    const int lr  = lane & 15;
    const int lk8 = lane >> 4;

    g_load_stage(0, 0, m0, n0, tid, smem_base);
    CP_COMMIT();
    g_load_stage(1, 1, m0, n0, tid, smem_base);
    CP_COMMIT();

    for (int it = 0; it < GEMM_ITERS; it++) {
        CP_WAIT(1);
        __syncthreads();

        if (it + 2 < GEMM_ITERS) {
            g_load_stage(it + 2, (it + 2) % 3, m0, n0, tid, smem_base);
            CP_COMMIT();
        }

        const uint32_t sbase = smem_base + (it % 3) * STG_B;
        #pragma unroll
        for (int ks = 0; ks < 4; ks++) {
            const int k8 = ks * 2 + lk8;
            uint32_t afr[2][4], bfr[4][4];
            #pragma unroll
            for (int mt = 0; mt < 2; mt++) {
                int row = wm * 32 + mt * 16 + lr;
                uint32_t ad = sbase + row * 128 + ((k8 ^ (row & 7)) << 4);
                LDSM_X4(afr[mt][0], afr[mt][1], afr[mt][2], afr[mt][3], ad);
            }
            #pragma unroll
            for (int np = 0; np < 4; np++) {
                int rn = wn * 64 + np * 16 + lr;
                uint32_t bd = sbase + OFF_B + rn * 128 + ((k8 ^ (rn & 7)) << 4);
                LDSM_X4(bfr[np][0], bfr[np][1], bfr[np][2], bfr[np][3], bd);
            }
            #pragma unroll
            for (int mt = 0; mt < 2; mt++)
                #pragma unroll
                for (int np = 0; np < 4; np++) {
                    MMA16816(acc[mt][2 * np],     afr[mt], bfr[np][0], bfr[np][2]);
                    MMA16816(acc[mt][2 * np + 1], afr[mt], bfr[np][1], bfr[np][3]);
                }
        }
    }

    const int cq = 2 * (lane & 3);
    float2 bv[8];
    #pragma unroll
    for (int nt = 0; nt < 8; nt++)
        bv[nt] = *(const float2*)(bias + n0 + wn * 64 + nt * 8 + cq);

    #pragma unroll
    for (int mt = 0; mt < 2; mt++) {
        int rg = m0 + wm * 32 + mt * 16 + (lane >> 2);
        #pragma unroll
        for (int nt = 0; nt < 8; nt++) {
            float* p = out + (size_t)rg * NSTATES + n0 + wn * 64 + nt * 8 + cq;
            float2 v0 = make_float2(acc[mt][nt][0] + bv[nt].x, acc[mt][nt][1] + bv[nt].y);
            float2 v1 = make_float2(acc[mt][nt][2] + bv[nt].x, acc[mt][nt][3] + bv[nt].y);
            *(float2*)p = v0;
            *(float2*)(p + (size_t)8 * NSTATES) = v1;
        }
    }
}

// ---------------- launch -----------------------------------------------------
extern "C" void kernel_launch(void* const* d_in, const int* in_sizes, int n_in,
                              void* d_out, int out_size)
{
    const int *csi, *ai;
    const float *emb, *W, *bias, *D0, *D1, *D2, *D3;
    if (in_sizes[4] == NSTATES) {
        csi = (const int*)d_in[0]; ai = (const int*)d_in[1];
        emb = (const float*)d_in[2]; W = (const float*)d_in[3];
        bias = (const float*)d_in[4];
        D0 = (const float*)d_in[5]; D1 = (const float*)d_in[6];
        D2 = (const float*)d_in[7]; D3 = (const float*)d_in[8];
    } else {
        csi = (const int*)d_in[0]; ai = (const int*)d_in[1];
        emb = (const float*)d_in[2];
        D0 = (const float*)d_in[3]; D1 = (const float*)d_in[4];
        D2 = (const float*)d_in[5]; D3 = (const float*)d_in[6];
        W = (const float*)d_in[7]; bias = (const float*)d_in[8];
    }

    float* out = (float*)d_out;
    float* gout;
    if ((long long)out_size >= (long long)B_SZ * (NSTATES + GTOT)) {
        gout = out + (size_t)B_SZ * NSTATES;
    } else {
        cudaGetSymbolAddress((void**)&gout, d_gscratch);
    }

    k_sort<<<1, 1024>>>(ai);
    k_convert<<<(CVT_TOT + 255) / 256, 256>>>(W, emb, D0, D1, D2, D3);

    cudaFuncSetAttribute(k_transition, cudaFuncAttributeMaxDynamicSharedMemorySize, TSM_TOTAL);
    dim3 tg(128, 12, NACT);
    k_transition<<<tg, 128, TSM_TOTAL>>>(csi, emb, gout);

    cudaFuncSetAttribute(k_logits, cudaFuncAttributeMaxDynamicSharedMemorySize, GSM_TOTAL);
    dim3 gg(NSTATES / 128, B_SZ / 128);
    k_logits<<<gg, 256, GSM_TOTAL>>>(bias, out);
}

// round 15
// speedup vs baseline: 1.0056x; 1.0056x over previous
#include <cuda_runtime.h>
#include <cuda_fp16.h>
#include <cstdint>

#define B_SZ    16384
#define NSTATES 4096
#define GTOT    768
#define NACT    4

// ---------------- mma / ldmatrix / cp.async helpers -------------------------
__device__ __forceinline__ uint32_t smem_to_u32(const void* p) {
    uint32_t a;
    asm("{ .reg .u64 t; cvta.to.shared.u64 t, %1; cvt.u32.u64 %0, t; }" : "=r"(a) : "l"(p));
    return a;
}
#define CP_ASYNC16(dst, src) \
    asm volatile("cp.async.cg.shared.global [%0], [%1], 16;" :: "r"(dst), "l"(src))
#define CP_COMMIT() asm volatile("cp.async.commit_group;" ::: "memory")
#define CP_WAIT(n)  asm volatile("cp.async.wait_group %0;" :: "n"(n) : "memory")

#define LDSM_X4(r0, r1, r2, r3, a) \
    asm volatile("ldmatrix.sync.aligned.m8n8.x4.shared.b16 {%0,%1,%2,%3}, [%4];" \
        : "=r"(r0), "=r"(r1), "=r"(r2), "=r"(r3) : "r"(a))

#define MMA16816(d, a, b0v, b1v) \
    asm volatile("mma.sync.aligned.m16n8k16.row.col.f32.f16.f16.f32 " \
        "{%0,%1,%2,%3}, {%4,%5,%6,%7}, {%8,%9}, {%0,%1,%2,%3};" \
        : "+f"((d)[0]), "+f"((d)[1]), "+f"((d)[2]), "+f"((d)[3]) \
        : "r"((a)[0]), "r"((a)[1]), "r"((a)[2]), "r"((a)[3]), "r"(b0v), "r"(b1v))

// ---------------- device scratch --------------------------------------------
__device__ int d_cnt[NACT];          // statically zero; k_prefix re-zeroes after read
__device__ int d_off[NACT + 1];
__device__ int d_cursor[NACT];
__device__ int d_perm[B_SZ];
__device__ float d_gscratch[(size_t)B_SZ * GTOT];
__device__ __half d_Ah[(size_t)B_SZ * GTOT];      // g_next in fp16
__device__ __half d_Wh[(size_t)NSTATES * GTOT];   // W in fp16
__device__ __half d_Eh[(size_t)NSTATES * GTOT];   // emb in fp16
__device__ __half d_D0h[4 * 256 * 256];
__device__ __half d_D1h[4 * 256 * 256];
__device__ __half d_D2h[4 * 128 * 128];
__device__ __half d_D3h[4 * 128 * 128];

// ---------------- multi-block counting sort ---------------------------------
__global__ void k_hist(const int* __restrict__ act) {
    __shared__ int c[NACT];
    const int t = threadIdx.x;
    const int lane = t & 31;
    if (t < NACT) c[t] = 0;
    __syncthreads();
    int i = blockIdx.x * 256 + t;                 // grid 64 x 256 == B_SZ
    int a = act[i];
    unsigned mask = __match_any_sync(0xffffffffu, a);
    if (lane == (__ffs(mask) - 1)) atomicAdd(&c[a], __popc(mask));
    __syncthreads();
    if (t < NACT && c[t] > 0) atomicAdd(&d_cnt[t], c[t]);
}

__global__ void k_prefix() {
    if (threadIdx.x == 0) {
        int s = 0;
        for (int a = 0; a < NACT; a++) {
            d_off[a] = s; d_cursor[a] = s; s += d_cnt[a];
            d_cnt[a] = 0;                          // reset for next graph replay
        }
        d_off[NACT] = s;
    }
}

// ---------------- scatter + fp32->fp16 convert in ONE launch -----------------
#define CVT_NW   (NSTATES * GTOT / 4)        // 786432 float4
#define CVT_ND01 (4 * 256 * 256 / 4)         // 65536
#define CVT_ND23 (4 * 128 * 128 / 4)         // 16384
#define CVT_TOT  (2 * CVT_NW + 2 * CVT_ND01 + 2 * CVT_ND23)
#define SCT_BLK  64
#define CVT_BLK  ((CVT_TOT + 255) / 256)

__global__ void k_scatcvt(const int* __restrict__ act,
                          const float* __restrict__ W, const float* __restrict__ E,
                          const float* __restrict__ D0, const float* __restrict__ D1,
                          const float* __restrict__ D2, const float* __restrict__ D3) {
    const int t = threadIdx.x;
    if (blockIdx.x < SCT_BLK) {                   // scatter
        const int lane = t & 31;
        int i = blockIdx.x * 256 + t;
        int a = act[i];
        unsigned mask = __match_any_sync(0xffffffffu, a);
        int leader = __ffs(mask) - 1;
        int rank = __popc(mask & ((1u << lane) - 1u));
        int base = 0;
        if (lane == leader) base = atomicAdd(&d_cursor[a], __popc(mask));
        base = __shfl_sync(0xffffffffu, base, leader);
        d_perm[base + rank] = i;
        return;
    }
    int i = (blockIdx.x - SCT_BLK) * 256 + t;     // convert
    const float* src; __half* dst;
    if (i < CVT_NW)                       { src = W;  dst = d_Wh; }
    else if ((i -= CVT_NW) < CVT_NW)      { src = E;  dst = d_Eh; }
    else if ((i -= CVT_NW) < CVT_ND01)    { src = D0; dst = d_D0h; }
    else if ((i -= CVT_ND01) < CVT_ND01)  { src = D1; dst = d_D1h; }
    else if ((i -= CVT_ND01) < CVT_ND23)  { src = D2; dst = d_D2h; }
    else if ((i -= CVT_ND23) < CVT_ND23)  { src = D3; dst = d_D3h; }
    else return;
    float4 w4 = ((const float4*)src)[i];
    ((__half2*)dst)[2 * i]     = __floats2half2_rn(w4.x, w4.y);
    ((__half2*)dst)[2 * i + 1] = __floats2half2_rn(w4.z, w4.w);
}

// ---------------- HMMA transition (M-tile 256) -------------------------------
// C[r,j] = sum_i Eh[state_r, moff+i] * Dh_a[jbase+j, i]; g_next = clip(g + C)
// Tile: 256 gathered rows x 64 cols, BK=64, 256 thr / 8 warps, warp 32x64.
#define TSM_PERM   0
#define TSM_STATE  1024
#define TSM_TILES  2048
#define TSTG_B     40960                 // A 32K + B 8K
#define TOFF_B     32768
#define TSM_TOTAL  (TSM_TILES + 2 * TSTG_B)   // 83968

__global__ void __launch_bounds__(256, 2)
k_transition(const int* __restrict__ csi,
             const float* __restrict__ emb,
             float* __restrict__ gout)
{
    extern __shared__ char smem[];
    const uint32_t smem_base = smem_to_u32(smem);
    int* permS   = (int*)(smem + TSM_PERM);
    int* stateS  = (int*)(smem + TSM_STATE);

    const int jt = blockIdx.y;
    const int a  = blockIdx.z;
    int jbase, moff, nf; const __half* Dh;
    if (jt < 4)       { jbase = jt * 64;        moff = 0;   nf = 256; Dh = d_D0h; }
    else if (jt < 8)  { jbase = (jt - 4) * 64;  moff = 256; nf = 256; Dh = d_D1h; }
    else if (jt < 10) { jbase = (jt - 8) * 64;  moff = 512; nf = 128; Dh = d_D2h; }
    else              { jbase = (jt - 10) * 64; moff = 640; nf = 128; Dh = d_D3h; }

    const int row0   = d_off[a] + blockIdx.x * 256;
    const int rowEnd = d_off[a + 1];
    if (row0 >= rowEnd) return;
    const __half* __restrict__ Da = Dh + (size_t)a * nf * nf;

    const int t = threadIdx.x;
    const int lane = t & 31;
    const int wid  = t >> 5;              // 0..7, each warp: 32 rows x 64 cols
    {
        int r = row0 + t;
        if (r < rowEnd) { int b = d_perm[r]; permS[t] = b; stateS[t] = csi[b]; }
        else            { permS[t] = -1;     stateS[t] = 0; }
    }
    __syncthreads();

    const int NK = nf / 64;

    // stage loader: A = gathered fp16 emb rows (1 row per thread), B = D rows
    auto load_stage = [&](int kk, int stg) {
        const int kc = kk * 64;
        const uint32_t sbase = smem_base + TSM_TILES + stg * TSTG_B;
        const __half* arow = d_Eh + (size_t)stateS[t] * GTOT + moff + kc;
        #pragma unroll
        for (int ck = 0; ck < 8; ck++) {
            uint32_t sw = t * 128 + ((ck ^ (t & 7)) << 4);
            CP_ASYNC16(sbase + sw, arow + ck * 8);
        }
        #pragma unroll
        for (int q = 0; q < 2; q++) {     // B: 512 ops / 256 thr
            int o  = t * 2 + q;
            int rn = o >> 3;              // 0..63
            int ck = o & 7;
            uint32_t sw = rn * 128 + ((ck ^ (rn & 7)) << 4);
            CP_ASYNC16(sbase + TOFF_B + sw, Da + (size_t)(jbase + rn) * nf + kc + ck * 8);
        }
    };

    float acc[2][8][4];
    #pragma unroll
    for (int mt = 0; mt < 2; mt++)
        #pragma unroll
        for (int nt = 0; nt < 8; nt++)
            #pragma unroll
            for (int q = 0; q < 4; q++) acc[mt][nt][q] = 0.f;

    const int lr  = lane & 15;
    const int lk8 = lane >> 4;

    load_stage(0, 0);
    CP_COMMIT();

    for (int kk = 0; kk < NK; kk++) {
        if (kk + 1 < NK) { load_stage(kk + 1, (kk + 1) & 1); CP_COMMIT(); CP_WAIT(1); }
        else             { CP_WAIT(0); }
        __syncthreads();

        const uint32_t sbase = smem_base + TSM_TILES + (kk & 1) * TSTG_B;
        #pragma unroll
        for (int ks = 0; ks < 4; ks++) {
            const int k8 = ks * 2 + lk8;
            uint32_t afr[2][4], bfr[4][4];
            #pragma unroll
            for (int mt = 0; mt < 2; mt++) {
                int row = wid * 32 + mt * 16 + lr;
                uint32_t ad = sbase + row * 128 + ((k8 ^ (row & 7)) << 4);
                LDSM_X4(afr[mt][0], afr[mt][1], afr[mt][2], afr[mt][3], ad);
            }
            #pragma unroll
            for (int np = 0; np < 4; np++) {
                int rn = np * 16 + lr;
                uint32_t bd = sbase + TOFF_B + rn * 128 + ((k8 ^ (rn & 7)) << 4);
                LDSM_X4(bfr[np][0], bfr[np][1], bfr[np][2], bfr[np][3], bd);
            }
            #pragma unroll
            for (int mt = 0; mt < 2; mt++)
                #pragma unroll
                for (int np = 0; np < 4; np++) {
                    MMA16816(acc[mt][2 * np],     afr[mt], bfr[np][0], bfr[np][2]);
                    MMA16816(acc[mt][2 * np + 1], afr[mt], bfr[np][1], bfr[np][3]);
                }
        }
        __syncthreads();
    }

    // epilogue: residual (fp32 emb) + clip; write gout fp32 + d_Ah fp16
    #pragma unroll
    for (int mt = 0; mt < 2; mt++) {
        int rl = wid * 32 + mt * 16 + (lane >> 2);
        #pragma unroll
        for (int half = 0; half < 2; half++) {
            int rr = rl + half * 8;
            int borig = permS[rr];
            if (borig < 0) continue;
            int state = stateS[rr];
            #pragma unroll
            for (int nt = 0; nt < 8; nt++) {
                int gcol = moff + jbase + nt * 8 + 2 * (lane & 3);
                float2 g2 = *(const float2*)(emb + (size_t)state * GTOT + gcol);
                float ox = fminf(fmaxf(g2.x + acc[mt][nt][2 * half],     -1.f), 1.f);
                float oy = fminf(fmaxf(g2.y + acc[mt][nt][2 * half + 1], -1.f), 1.f);
                *(float2*)(gout + (size_t)borig * GTOT + gcol) = make_float2(ox, oy);
                *(__half2*)(d_Ah + (size_t)borig * GTOT + gcol) = __floats2half2_rn(ox, oy);
            }
        }
    }
}

// ---------------- HMMA logits GEMM (R8 config: at legacy-pipe floor) ---------
#define GEMM_ITERS 12
#define STG_B      32768
#define OFF_B      16384
#define GSM_TOTAL  (3 * STG_B)               // 96 KB

__device__ __forceinline__ void g_load_stage(int it, int stg, int m0, int n0,
                                             int tid, uint32_t smem_base) {
    const int kc = it * 64;
    const int row = tid >> 1;
    const int cb  = (tid & 1) * 4;
    const uint32_t sbase = smem_base + stg * STG_B;
    const __half* ah = d_Ah + (size_t)(m0 + row) * GTOT + kc;
    const __half* bw = d_Wh + (size_t)(n0 + row) * GTOT + kc;
    #pragma unroll
    for (int c = 0; c < 4; c++) {
        int ck = cb + c;
        uint32_t sw = row * 128 + ((ck ^ (row & 7)) << 4);
        CP_ASYNC16(sbase + sw,          ah + ck * 8);
        CP_ASYNC16(sbase + OFF_B + sw,  bw + ck * 8);
    }
}

__global__ void __launch_bounds__(256, 2)
k_logits(const float* __restrict__ bias, float* __restrict__ out)
{
    extern __shared__ char smem[];
    const uint32_t smem_base = smem_to_u32(smem);
    const int tid  = threadIdx.x;
    const int lane = tid & 31;
    const int wid  = tid >> 5;
    const int wm   = wid >> 1;
    const int wn   = wid & 1;
    const int m0 = blockIdx.y * 128;
    const int n0 = blockIdx.x * 128;

    float acc[2][8][4];
    #pragma unroll
    for (int mt = 0; mt < 2; mt++)
        #pragma unroll
        for (int nt = 0; nt < 8; nt++)
            #pragma unroll
            for (int q = 0; q < 4; q++) acc[mt][nt][q] = 0.f;

    const int lr  = lane & 15;
    const int lk8 = lane >> 4;

    g_load_stage(0, 0, m0, n0, tid, smem_base);
    CP_COMMIT();
    g_load_stage(1, 1, m0, n0, tid, smem_base);
    CP_COMMIT();

    for (int it = 0; it < GEMM_ITERS; it++) {
        CP_WAIT(1);
        __syncthreads();

        if (it + 2 < GEMM_ITERS) {
            g_load_stage(it + 2, (it + 2) % 3, m0, n0, tid, smem_base);
            CP_COMMIT();
        }

        const uint32_t sbase = smem_base + (it % 3) * STG_B;
        #pragma unroll
        for (int ks = 0; ks < 4; ks++) {
            const int k8 = ks * 2 + lk8;
            uint32_t afr[2][4], bfr[4][4];
            #pragma unroll
            for (int mt = 0; mt < 2; mt++) {
                int row = wm * 32 + mt * 16 + lr;
                uint32_t ad = sbase + row * 128 + ((k8 ^ (row & 7)) << 4);
                LDSM_X4(afr[mt][0], afr[mt][1], afr[mt][2], afr[mt][3], ad);
            }
            #pragma unroll
            for (int np = 0; np < 4; np++) {
                int rn = wn * 64 + np * 16 + lr;
                uint32_t bd = sbase + OFF_B + rn * 128 + ((k8 ^ (rn & 7)) << 4);
                LDSM_X4(bfr[np][0], bfr[np][1], bfr[np][2], bfr[np][3], bd);
            }
            #pragma unroll
            for (int mt = 0; mt < 2; mt++)
                #pragma unroll
                for (int np = 0; np < 4; np++) {
                    MMA16816(acc[mt][2 * np],     afr[mt], bfr[np][0], bfr[np][2]);
                    MMA16816(acc[mt][2 * np + 1], afr[mt], bfr[np][1], bfr[np][3]);
                }
        }
    }

    const int cq = 2 * (lane & 3);
    float2 bv[8];
    #pragma unroll
    for (int nt = 0; nt < 8; nt++)
        bv[nt] = *(const float2*)(bias + n0 + wn * 64 + nt * 8 + cq);

    #pragma unroll
    for (int mt = 0; mt < 2; mt++) {
        int rg = m0 + wm * 32 + mt * 16 + (lane >> 2);
        #pragma unroll
        for (int nt = 0; nt < 8; nt++) {
            float* p = out + (size_t)rg * NSTATES + n0 + wn * 64 + nt * 8 + cq;
            float2 v0 = make_float2(acc[mt][nt][0] + bv[nt].x, acc[mt][nt][1] + bv[nt].y);
            float2 v1 = make_float2(acc[mt][nt][2] + bv[nt].x, acc[mt][nt][3] + bv[nt].y);
            *(float2*)p = v0;
            *(float2*)(p + (size_t)8 * NSTATES) = v1;
        }
    }
}

// ---------------- launch -----------------------------------------------------
extern "C" void kernel_launch(void* const* d_in, const int* in_sizes, int n_in,
                              void* d_out, int out_size)
{
    const int *csi, *ai;
    const float *emb, *W, *bias, *D0, *D1, *D2, *D3;
    if (in_sizes[4] == NSTATES) {
        csi = (const int*)d_in[0]; ai = (const int*)d_in[1];
        emb = (const float*)d_in[2]; W = (const float*)d_in[3];
        bias = (const float*)d_in[4];
        D0 = (const float*)d_in[5]; D1 = (const float*)d_in[6];
        D2 = (const float*)d_in[7]; D3 = (const float*)d_in[8];
    } else {
        csi = (const int*)d_in[0]; ai = (const int*)d_in[1];
        emb = (const float*)d_in[2];
        D0 = (const float*)d_in[3]; D1 = (const float*)d_in[4];
        D2 = (const float*)d_in[5]; D3 = (const float*)d_in[6];
        W = (const float*)d_in[7]; bias = (const float*)d_in[8];
    }

    float* out = (float*)d_out;
    float* gout;
    if ((long long)out_size >= (long long)B_SZ * (NSTATES + GTOT)) {
        gout = out + (size_t)B_SZ * NSTATES;
    } else {
        cudaGetSymbolAddress((void**)&gout, d_gscratch);
    }

    k_hist<<<SCT_BLK, 256>>>(ai);
    k_prefix<<<1, 32>>>();
    k_scatcvt<<<SCT_BLK + CVT_BLK, 256>>>(ai, W, emb, D0, D1, D2, D3);

    cudaFuncSetAttribute(k_transition, cudaFuncAttributeMaxDynamicSharedMemorySize, TSM_TOTAL);
    dim3 tg(B_SZ / 256, 12, NACT);
    k_transition<<<tg, 256, TSM_TOTAL>>>(csi, emb, gout);

    cudaFuncSetAttribute(k_logits, cudaFuncAttributeMaxDynamicSharedMemorySize, GSM_TOTAL);
    dim3 gg(NSTATES / 128, B_SZ / 128);
    k_logits<<<gg, 256, GSM_TOTAL>>>(bias, out);
}

// round 16
// speedup vs baseline: 1.0221x; 1.0164x over previous
#include <cuda_runtime.h>
#include <cuda_fp16.h>
#include <cstdint>

#define B_SZ    16384
#define NSTATES 4096
#define GTOT    768
#define NACT    4

// ---------------- mma / ldmatrix / cp.async helpers -------------------------
__device__ __forceinline__ uint32_t smem_to_u32(const void* p) {
    uint32_t a;
    asm("{ .reg .u64 t; cvta.to.shared.u64 t, %1; cvt.u32.u64 %0, t; }" : "=r"(a) : "l"(p));
    return a;
}
#define CP_ASYNC16(dst, src) \
    asm volatile("cp.async.cg.shared.global [%0], [%1], 16;" :: "r"(dst), "l"(src))
#define CP_COMMIT() asm volatile("cp.async.commit_group;" ::: "memory")
#define CP_WAIT(n)  asm volatile("cp.async.wait_group %0;" :: "n"(n) : "memory")

#define LDSM_X4(r0, r1, r2, r3, a) \
    asm volatile("ldmatrix.sync.aligned.m8n8.x4.shared.b16 {%0,%1,%2,%3}, [%4];" \
        : "=r"(r0), "=r"(r1), "=r"(r2), "=r"(r3) : "r"(a))

#define MMA16816(d, a, b0v, b1v) \
    asm volatile("mma.sync.aligned.m16n8k16.row.col.f32.f16.f16.f32 " \
        "{%0,%1,%2,%3}, {%4,%5,%6,%7}, {%8,%9}, {%0,%1,%2,%3};" \
        : "+f"((d)[0]), "+f"((d)[1]), "+f"((d)[2]), "+f"((d)[3]) \
        : "r"((a)[0]), "r"((a)[1]), "r"((a)[2]), "r"((a)[3]), "r"(b0v), "r"(b1v))

// ---------------- device scratch --------------------------------------------
__device__ int d_cnt[NACT];          // statically zero; k_prefix re-zeroes after read
__device__ int d_off[NACT + 1];
__device__ int d_cursor[NACT];
__device__ int d_perm[B_SZ];
__device__ float d_gscratch[(size_t)B_SZ * GTOT];
__device__ __half d_Ah[(size_t)B_SZ * GTOT];      // g_next in fp16
__device__ __half d_Wh[(size_t)NSTATES * GTOT];   // W in fp16
__device__ __half d_Eh[(size_t)NSTATES * GTOT];   // emb in fp16
__device__ __half d_D0h[4 * 256 * 256];
__device__ __half d_D1h[4 * 256 * 256];
__device__ __half d_D2h[4 * 128 * 128];
__device__ __half d_D3h[4 * 128 * 128];

// ---------------- multi-block counting sort ---------------------------------
__global__ void k_hist(const int* __restrict__ act) {
    __shared__ int c[NACT];
    const int t = threadIdx.x;
    const int lane = t & 31;
    if (t < NACT) c[t] = 0;
    __syncthreads();
    int i = blockIdx.x * 256 + t;                 // grid 64 x 256 == B_SZ
    int a = act[i];
    unsigned mask = __match_any_sync(0xffffffffu, a);
    if (lane == (__ffs(mask) - 1)) atomicAdd(&c[a], __popc(mask));
    __syncthreads();
    if (t < NACT && c[t] > 0) atomicAdd(&d_cnt[t], c[t]);
}

__global__ void k_prefix() {
    if (threadIdx.x == 0) {
        int s = 0;
        for (int a = 0; a < NACT; a++) {
            d_off[a] = s; d_cursor[a] = s; s += d_cnt[a];
            d_cnt[a] = 0;                          // reset for next graph replay
        }
        d_off[NACT] = s;
    }
}

// ---------------- scatter + fp32->fp16 convert in ONE launch -----------------
#define CVT_NW   (NSTATES * GTOT / 4)        // 786432 float4
#define CVT_ND01 (4 * 256 * 256 / 4)         // 65536
#define CVT_ND23 (4 * 128 * 128 / 4)         // 16384
#define CVT_TOT  (2 * CVT_NW + 2 * CVT_ND01 + 2 * CVT_ND23)
#define SCT_BLK  64
#define CVT_BLK  ((CVT_TOT + 255) / 256)

__global__ void k_scatcvt(const int* __restrict__ act,
                          const float* __restrict__ W, const float* __restrict__ E,
                          const float* __restrict__ D0, const float* __restrict__ D1,
                          const float* __restrict__ D2, const float* __restrict__ D3) {
    const int t = threadIdx.x;
    if (blockIdx.x < SCT_BLK) {                   // scatter
        const int lane = t & 31;
        int i = blockIdx.x * 256 + t;
        int a = act[i];
        unsigned mask = __match_any_sync(0xffffffffu, a);
        int leader = __ffs(mask) - 1;
        int rank = __popc(mask & ((1u << lane) - 1u));
        int base = 0;
        if (lane == leader) base = atomicAdd(&d_cursor[a], __popc(mask));
        base = __shfl_sync(0xffffffffu, base, leader);
        d_perm[base + rank] = i;
        return;
    }
    int i = (blockIdx.x - SCT_BLK) * 256 + t;     // convert
    const float* src; __half* dst;
    if (i < CVT_NW)                       { src = W;  dst = d_Wh; }
    else if ((i -= CVT_NW) < CVT_NW)      { src = E;  dst = d_Eh; }
    else if ((i -= CVT_NW) < CVT_ND01)    { src = D0; dst = d_D0h; }
    else if ((i -= CVT_ND01) < CVT_ND01)  { src = D1; dst = d_D1h; }
    else if ((i -= CVT_ND01) < CVT_ND23)  { src = D2; dst = d_D2h; }
    else if ((i -= CVT_ND23) < CVT_ND23)  { src = D3; dst = d_D3h; }
    else return;
    float4 w4 = ((const float4*)src)[i];
    ((__half2*)dst)[2 * i]     = __floats2half2_rn(w4.x, w4.y);
    ((__half2*)dst)[2 * i + 1] = __floats2half2_rn(w4.z, w4.w);
}

// ---------------- HMMA transition: A-resident, j-tile loop -------------------
// Block = (128 gathered rows) x (one module, all its j-tiles), one action.
// A slice (128 x nf fp16) loaded to smem ONCE; B 64x64 chunks double-buffered.
// 256 thr / 8 warps, warp tile 32x32 (4M x 2N over 128x64 per j-tile).
#define TSM_PERM   0
#define TSM_STATE  512
#define TSM_TILES  1024
#define TA_CHUNK   16384                     // one 128x64 fp16 A chunk
#define TB_STG     8192                      // one 64x64 fp16 B chunk
#define TOFF_B     (TSM_TILES + 4 * TA_CHUNK)         // A: up to 4 chunks (nf=256)
#define TSM_TOTAL  (TOFF_B + 2 * TB_STG)              // 83968

__global__ void __launch_bounds__(256, 2)
k_transition(const int* __restrict__ csi,
             const float* __restrict__ emb,
             float* __restrict__ gout)
{
    extern __shared__ char smem[];
    const uint32_t smem_base = smem_to_u32(smem);
    int* permS   = (int*)(smem + TSM_PERM);
    int* stateS  = (int*)(smem + TSM_STATE);

    const int mod = blockIdx.y;
    const int a   = blockIdx.z;
    int moff, nf; const __half* Dh;
    switch (mod) {
        case 0:  moff = 0;   nf = 256; Dh = d_D0h; break;
        case 1:  moff = 256; nf = 256; Dh = d_D1h; break;
        case 2:  moff = 512; nf = 128; Dh = d_D2h; break;
        default: moff = 640; nf = 128; Dh = d_D3h; break;
    }

    const int row0   = d_off[a] + blockIdx.x * 128;
    const int rowEnd = d_off[a + 1];
    if (row0 >= rowEnd) return;
    const __half* __restrict__ Da = Dh + (size_t)a * nf * nf;

    const int t = threadIdx.x;
    const int lane = t & 31;
    const int wid  = t >> 5;
    const int wm   = wid >> 1;            // 0..3 -> 32 rows
    const int wn   = wid & 1;             // 0..1 -> 32 cols
    if (t < 128) {
        int r = row0 + t;
        if (r < rowEnd) { int b = d_perm[r]; permS[t] = b; stateS[t] = csi[b]; }
        else            { permS[t] = -1;     stateS[t] = 0; }
    }
    __syncthreads();

    const int NK  = nf / 64;              // k-chunks per module (4 or 2)
    const int NJT = nf / 64;              // j-tiles per module (4 or 2)
    const int NIT = NJT * NK;

    // ---- load full A slice (NK chunks) once ----
    for (int c = 0; c < NK; c++) {
        const uint32_t abase = smem_base + TSM_TILES + c * TA_CHUNK;
        #pragma unroll
        for (int q = 0; q < 4; q++) {     // 1024 ops / 256 thr
            int o   = t * 4 + q;
            int row = o >> 3;             // 0..127
            int ck  = o & 7;
            uint32_t sw = row * 128 + ((ck ^ (row & 7)) << 4);
            CP_ASYNC16(abase + sw, d_Eh + (size_t)stateS[row] * GTOT + moff + c * 64 + ck * 8);
        }
    }
    CP_COMMIT();                          // group: A

    // B chunk loader: j-tile jt, k-chunk k, stage s
    auto load_b = [&](int it, int s) {
        const int jt = it / NK;
        const int k  = it % NK;
        const uint32_t bbase = smem_base + TOFF_B + s * TB_STG;
        #pragma unroll
        for (int q = 0; q < 2; q++) {     // 512 ops / 256 thr
            int o  = t * 2 + q;
            int rn = o >> 3;              // 0..63
            int ck = o & 7;
            uint32_t sw = rn * 128 + ((ck ^ (rn & 7)) << 4);
            CP_ASYNC16(bbase + sw, Da + (size_t)(jt * 64 + rn) * nf + k * 64 + ck * 8);
        }
    };

    load_b(0, 0);
    CP_COMMIT();

    float acc[2][4][4];
    #pragma unroll
    for (int mt = 0; mt < 2; mt++)
        #pragma unroll
        for (int nt = 0; nt < 4; nt++)
            #pragma unroll
            for (int q = 0; q < 4; q++) acc[mt][nt][q] = 0.f;

    const int lr  = lane & 15;
    const int lk8 = lane >> 4;

    for (int it = 0; it < NIT; it++) {
        if (it + 1 < NIT) { load_b(it + 1, (it + 1) & 1); CP_COMMIT(); CP_WAIT(1); }
        else              { CP_WAIT(0); }
        __syncthreads();                  // A + B(it) visible

        const int k = it % NK;
        const uint32_t abase = smem_base + TSM_TILES + k * TA_CHUNK;
        const uint32_t bbase = smem_base + TOFF_B + (it & 1) * TB_STG;
        #pragma unroll
        for (int ks = 0; ks < 4; ks++) {
            const int k8 = ks * 2 + lk8;
            uint32_t afr[2][4], bfr[2][4];
            #pragma unroll
            for (int mt = 0; mt < 2; mt++) {
                int row = wm * 32 + mt * 16 + lr;
                uint32_t ad = abase + row * 128 + ((k8 ^ (row & 7)) << 4);
                LDSM_X4(afr[mt][0], afr[mt][1], afr[mt][2], afr[mt][3], ad);
            }
            #pragma unroll
            for (int np = 0; np < 2; np++) {
                int rn = wn * 32 + np * 16 + lr;
                uint32_t bd = bbase + rn * 128 + ((k8 ^ (rn & 7)) << 4);
                LDSM_X4(bfr[np][0], bfr[np][1], bfr[np][2], bfr[np][3], bd);
            }
            #pragma unroll
            for (int mt = 0; mt < 2; mt++)
                #pragma unroll
                for (int np = 0; np < 2; np++) {
                    MMA16816(acc[mt][2 * np],     afr[mt], bfr[np][0], bfr[np][2]);
                    MMA16816(acc[mt][2 * np + 1], afr[mt], bfr[np][1], bfr[np][3]);
                }
        }

        if (k == NK - 1) {
            // ---- epilogue for j-tile it/NK: residual + clip, write fp32 + fp16
            const int jbase = (it / NK) * 64;
            #pragma unroll
            for (int mt = 0; mt < 2; mt++) {
                #pragma unroll
                for (int half = 0; half < 2; half++) {
                    int rr = wm * 32 + mt * 16 + half * 8 + (lane >> 2);
                    int borig = permS[rr];
                    if (borig >= 0) {
                        int state = stateS[rr];
                        #pragma unroll
                        for (int nt = 0; nt < 4; nt++) {
                            int gcol = moff + jbase + wn * 32 + nt * 8 + 2 * (lane & 3);
                            float2 g2 = *(const float2*)(emb + (size_t)state * GTOT + gcol);
                            float ox = fminf(fmaxf(g2.x + acc[mt][nt][2 * half],     -1.f), 1.f);
                            float oy = fminf(fmaxf(g2.y + acc[mt][nt][2 * half + 1], -1.f), 1.f);
                            *(float2*)(gout + (size_t)borig * GTOT + gcol) = make_float2(ox, oy);
                            *(__half2*)(d_Ah + (size_t)borig * GTOT + gcol) = __floats2half2_rn(ox, oy);
                        }
                    }
                }
            }
            #pragma unroll
            for (int mt = 0; mt < 2; mt++)
                #pragma unroll
                for (int nt = 0; nt < 4; nt++)
                    #pragma unroll
                    for (int q = 0; q < 4; q++) acc[mt][nt][q] = 0.f;
        }
        __syncthreads();                  // all warps done with B stage (it&1)
    }
}

// ---------------- HMMA logits GEMM (R8 config: at legacy-pipe floor) ---------
#define GEMM_ITERS 12
#define STG_B      32768
#define OFF_B      16384
#define GSM_TOTAL  (3 * STG_B)               // 96 KB

__device__ __forceinline__ void g_load_stage(int it, int stg, int m0, int n0,
                                             int tid, uint32_t smem_base) {
    const int kc = it * 64;
    const int row = tid >> 1;
    const int cb  = (tid & 1) * 4;
    const uint32_t sbase = smem_base + stg * STG_B;
    const __half* ah = d_Ah + (size_t)(m0 + row) * GTOT + kc;
    const __half* bw = d_Wh + (size_t)(n0 + row) * GTOT + kc;
    #pragma unroll
    for (int c = 0; c < 4; c++) {
        int ck = cb + c;
        uint32_t sw = row * 128 + ((ck ^ (row & 7)) << 4);
        CP_ASYNC16(sbase + sw,          ah + ck * 8);
        CP_ASYNC16(sbase + OFF_B + sw,  bw + ck * 8);
    }
}

__global__ void __launch_bounds__(256, 2)
k_logits(const float* __restrict__ bias, float* __restrict__ out)
{
    extern __shared__ char smem[];
    const uint32_t smem_base = smem_to_u32(smem);
    const int tid  = threadIdx.x;
    const int lane = tid & 31;
    const int wid  = tid >> 5;
    const int wm   = wid >> 1;
    const int wn   = wid & 1;
    const int m0 = blockIdx.y * 128;
    const int n0 = blockIdx.x * 128;

    float acc[2][8][4];
    #pragma unroll
    for (int mt = 0; mt < 2; mt++)
        #pragma unroll
        for (int nt = 0; nt < 8; nt++)
            #pragma unroll
            for (int q = 0; q < 4; q++) acc[mt][nt][q] = 0.f;

    const int lr  = lane & 15;
    const int lk8 = lane >> 4;

    g_load_stage(0, 0, m0, n0, tid, smem_base);
    CP_COMMIT();
    g_load_stage(1, 1, m0, n0, tid, smem_base);
    CP_COMMIT();

    for (int it = 0; it < GEMM_ITERS; it++) {
        CP_WAIT(1);
        __syncthreads();

        if (it + 2 < GEMM_ITERS) {
            g_load_stage(it + 2, (it + 2) % 3, m0, n0, tid, smem_base);
            CP_COMMIT();
        }

        const uint32_t sbase = smem_base + (it % 3) * STG_B;
        #pragma unroll
        for (int ks = 0; ks < 4; ks++) {
            const int k8 = ks * 2 + lk8;
            uint32_t afr[2][4], bfr[4][4];
            #pragma unroll
            for (int mt = 0; mt < 2; mt++) {
                int row = wm * 32 + mt * 16 + lr;
                uint32_t ad = sbase + row * 128 + ((k8 ^ (row & 7)) << 4);
                LDSM_X4(afr[mt][0], afr[mt][1], afr[mt][2], afr[mt][3], ad);
            }
            #pragma unroll
            for (int np = 0; np < 4; np++) {
                int rn = wn * 64 + np * 16 + lr;
                uint32_t bd = sbase + OFF_B + rn * 128 + ((k8 ^ (rn & 7)) << 4);
                LDSM_X4(bfr[np][0], bfr[np][1], bfr[np][2], bfr[np][3], bd);
            }
            #pragma unroll
            for (int mt = 0; mt < 2; mt++)
                #pragma unroll
                for (int np = 0; np < 4; np++) {
                    MMA16816(acc[mt][2 * np],     afr[mt], bfr[np][0], bfr[np][2]);
                    MMA16816(acc[mt][2 * np + 1], afr[mt], bfr[np][1], bfr[np][3]);
                }
        }
    }

    const int cq = 2 * (lane & 3);
    float2 bv[8];
    #pragma unroll
    for (int nt = 0; nt < 8; nt++)
        bv[nt] = *(const float2*)(bias + n0 + wn * 64 + nt * 8 + cq);

    #pragma unroll
    for (int mt = 0; mt < 2; mt++) {
        int rg = m0 + wm * 32 + mt * 16 + (lane >> 2);
        #pragma unroll
        for (int nt = 0; nt < 8; nt++) {
            float* p = out + (size_t)rg * NSTATES + n0 + wn * 64 + nt * 8 + cq;
            float2 v0 = make_float2(acc[mt][nt][0] + bv[nt].x, acc[mt][nt][1] + bv[nt].y);
            float2 v1 = make_float2(acc[mt][nt][2] + bv[nt].x, acc[mt][nt][3] + bv[nt].y);
            *(float2*)p = v0;
            *(float2*)(p + (size_t)8 * NSTATES) = v1;
        }
    }
}

// ---------------- launch -----------------------------------------------------
extern "C" void kernel_launch(void* const* d_in, const int* in_sizes, int n_in,
                              void* d_out, int out_size)
{
    const int *csi, *ai;
    const float *emb, *W, *bias, *D0, *D1, *D2, *D3;
    if (in_sizes[4] == NSTATES) {
        csi = (const int*)d_in[0]; ai = (const int*)d_in[1];
        emb = (const float*)d_in[2]; W = (const float*)d_in[3];
        bias = (const float*)d_in[4];
        D0 = (const float*)d_in[5]; D1 = (const float*)d_in[6];
        D2 = (const float*)d_in[7]; D3 = (const float*)d_in[8];
    } else {
        csi = (const int*)d_in[0]; ai = (const int*)d_in[1];
        emb = (const float*)d_in[2];
        D0 = (const float*)d_in[3]; D1 = (const float*)d_in[4];
        D2 = (const float*)d_in[5]; D3 = (const float*)d_in[6];
        W = (const float*)d_in[7]; bias = (const float*)d_in[8];
    }

    float* out = (float*)d_out;
    float* gout;
    if ((long long)out_size >= (long long)B_SZ * (NSTATES + GTOT)) {
        gout = out + (size_t)B_SZ * NSTATES;
    } else {
        cudaGetSymbolAddress((void**)&gout, d_gscratch);
    }

    k_hist<<<SCT_BLK, 256>>>(ai);
    k_prefix<<<1, 32>>>();
    k_scatcvt<<<SCT_BLK + CVT_BLK, 256>>>(ai, W, emb, D0, D1, D2, D3);

    cudaFuncSetAttribute(k_transition, cudaFuncAttributeMaxDynamicSharedMemorySize, TSM_TOTAL);
    dim3 tg(B_SZ / 128, 4, NACT);
    k_transition<<<tg, 256, TSM_TOTAL>>>(csi, emb, gout);

    cudaFuncSetAttribute(k_logits, cudaFuncAttributeMaxDynamicSharedMemorySize, GSM_TOTAL);
    dim3 gg(NSTATES / 128, B_SZ / 128);
    k_logits<<<gg, 256, GSM_TOTAL>>>(bias, out);
}